// round 12
// baseline (speedup 1.0000x reference)
#include <cuda_runtime.h>
#include <cstdint>

// B=8, C=16, H=512, W=512, M=N=15
//   K:     [128, 16, 16]  f32
//   basis: [262144, 16, 16] f32, separable: basis[h*W+w,p,q] = Bu[h,p]*Bv[w,q]
//   out:   [128, 512, 512] f32
//
// Bu[h,p] = sum_q basis[h*W, p, q]; Bv[w,q] = sum_p basis[w, p, q]
// T[bc,p,w] = sum_q K[bc,p,q]*Bv[w,q];  out[bc,h,w] = sum_p Bu[h,p]*T[bc,p,w]

#define HH 512
#define WW 512
#define PP 16
#define QQ 16
#define BC 128
#define SROWS 16   // h-rows per block (all threads share them)

__device__ float g_But[PP * HH];      // Bu transposed: [p][h], 32 KB
__device__ float g_BvT[QQ * WW];      // Bv transposed: [q][w], 32 KB
__device__ float g_T[BC * PP * WW];   // T: [bc][p][w], 4 MB (L2-resident)

__device__ __forceinline__ unsigned long long pk(float a, float b) {
    unsigned long long r;
    asm("mov.b64 %0, {%1, %2};" : "=l"(r) : "f"(a), "f"(b));
    return r;
}
__device__ __forceinline__ void fma2(unsigned long long& d, unsigned long long a,
                                     unsigned long long b) {
    asm("fma.rn.f32x2 %0, %1, %2, %0;" : "+l"(d) : "l"(a), "l"(b));
}
__device__ __forceinline__ void unpk(unsigned long long v, float& a, float& b) {
    asm("mov.b64 {%0, %1}, %2;" : "=f"(a), "=f"(b) : "l"(v));
}

// ---------------------------------------------------------------------------
// Kernel A: extraction. Warp-per-row, coalesced loads, shfl reductions.
// ---------------------------------------------------------------------------
__global__ __launch_bounds__(256) void extract_factors(const float* __restrict__ basis) {
    int warp = threadIdx.x >> 5, lane = threadIdx.x & 31;
    if (blockIdx.x < 64) {
        int h = blockIdx.x * 8 + warp;
        const float4* r4 = reinterpret_cast<const float4*>(basis + (size_t)h * WW * (PP * QQ));
        float4 a = r4[lane * 2];
        float4 b = r4[lane * 2 + 1];
        float s = (a.x + a.y) + (a.z + a.w) + (b.x + b.y) + (b.z + b.w);
        s += __shfl_xor_sync(0xffffffffu, s, 1);   // lanes (2k,2k+1) cover p=k
        if ((lane & 1) == 0) g_But[(lane >> 1) * HH + h] = s;
    } else {
        int w = (blockIdx.x - 64) * 8 + warp;
        const float4* r4 = reinterpret_cast<const float4*>(basis + (size_t)w * (PP * QQ));
        float4 a = r4[lane * 2];
        float4 b = r4[lane * 2 + 1];
        #pragma unroll
        for (int off = 2; off <= 16; off <<= 1) {
            a.x += __shfl_xor_sync(0xffffffffu, a.x, off);
            a.y += __shfl_xor_sync(0xffffffffu, a.y, off);
            a.z += __shfl_xor_sync(0xffffffffu, a.z, off);
            a.w += __shfl_xor_sync(0xffffffffu, a.w, off);
            b.x += __shfl_xor_sync(0xffffffffu, b.x, off);
            b.y += __shfl_xor_sync(0xffffffffu, b.y, off);
            b.z += __shfl_xor_sync(0xffffffffu, b.z, off);
            b.w += __shfl_xor_sync(0xffffffffu, b.w, off);
        }
        if (lane < 2) {
            int q0 = lane * 8;
            g_BvT[(q0 + 0) * WW + w] = a.x;
            g_BvT[(q0 + 1) * WW + w] = a.y;
            g_BvT[(q0 + 2) * WW + w] = a.z;
            g_BvT[(q0 + 3) * WW + w] = a.w;
            g_BvT[(q0 + 4) * WW + w] = b.x;
            g_BvT[(q0 + 5) * WW + w] = b.y;
            g_BvT[(q0 + 6) * WW + w] = b.z;
            g_BvT[(q0 + 7) * WW + w] = b.w;
        }
    }
}

// ---------------------------------------------------------------------------
// Kernel B: T[bc,p,w] = sum_q K[bc,p,q] * Bv[w,q]. grid (2, BC), 256 threads.
// ---------------------------------------------------------------------------
__global__ __launch_bounds__(256) void stage1(const float* __restrict__ K) {
    int bc = blockIdx.y;
    int w = blockIdx.x * 256 + threadIdx.x;

    __shared__ float sK[PP * QQ];
    sK[threadIdx.x] = K[(size_t)bc * (PP * QQ) + threadIdx.x];

    float rv[QQ];
    #pragma unroll
    for (int q = 0; q < QQ; ++q) rv[q] = g_BvT[q * WW + w];
    __syncthreads();

    float* tb = g_T + (size_t)bc * PP * WW + w;
    #pragma unroll
    for (int p = 0; p < PP; ++p) {
        float s = 0.f;
        #pragma unroll
        for (int q = 0; q < QQ; ++q) s = fmaf(sK[p * QQ + q], rv[q], s);
        tb[p * WW] = s;
    }
}

// ---------------------------------------------------------------------------
// Kernel C: out[bc,h,w] = sum_p Bu[h,p] * T[bc,p,w]
//   grid (HH/SROWS=32, BC), 128 threads. NO shared memory in hot loop.
//   Every thread owns ALL 16 rows of the strip x 4 w (w = 4t..4t+3).
//   Per p: 4 block-uniform LDG.128 (Bu, natural h-pairs) +
//          1 coalesced LDG.128 (T) + 4 dup movs + 32 FFMA2 (32 chains).
// ---------------------------------------------------------------------------
__global__ __launch_bounds__(128) void fused_stage(float* __restrict__ out) {
    int bc = blockIdx.y;
    int h0 = blockIdx.x * SROWS;
    int t = threadIdx.x;

    const float4* Bu4 = reinterpret_cast<const float4*>(g_But);
    const float4* T4  = reinterpret_cast<const float4*>(g_T + (size_t)bc * PP * WW);

    unsigned long long acc[8][4];   // [h-pair][w]
    #pragma unroll
    for (int j = 0; j < 8; ++j)
        #pragma unroll
        for (int w = 0; w < 4; ++w) acc[j][w] = 0ull;

    #pragma unroll
    for (int p = 0; p < PP; ++p) {
        // Bu rows h0..h0+15: 4 uniform LDG.128 -> 8 natural (h,h+1) pairs
        int bidx = (p * HH + h0) >> 2;
        float4 bu0 = Bu4[bidx + 0];
        float4 bu1 = Bu4[bidx + 1];
        float4 bu2 = Bu4[bidx + 2];
        float4 bu3 = Bu4[bidx + 3];
        unsigned long long bp[8];
        bp[0] = pk(bu0.x, bu0.y); bp[1] = pk(bu0.z, bu0.w);
        bp[2] = pk(bu1.x, bu1.y); bp[3] = pk(bu1.z, bu1.w);
        bp[4] = pk(bu2.x, bu2.y); bp[5] = pk(bu2.z, bu2.w);
        bp[6] = pk(bu3.x, bu3.y); bp[7] = pk(bu3.z, bu3.w);

        // T[p][4t..4t+3]: coalesced LDG.128, dup'd per w
        float4 tv = T4[p * (WW / 4) + t];
        unsigned long long td[4];
        td[0] = pk(tv.x, tv.x);
        td[1] = pk(tv.y, tv.y);
        td[2] = pk(tv.z, tv.z);
        td[3] = pk(tv.w, tv.w);

        #pragma unroll
        for (int j = 0; j < 8; ++j)
            #pragma unroll
            for (int w = 0; w < 4; ++w)
                fma2(acc[j][w], bp[j], td[w]);
    }

    // Store 16 rows x 4 w (float4 per row, coalesced across threads)
    float* obase = out + (size_t)bc * HH * WW + (size_t)h0 * WW + 4 * t;
    #pragma unroll
    for (int j = 0; j < 8; ++j) {
        float e0, o0, e1, o1, e2, o2, e3, o3;
        unpk(acc[j][0], e0, o0);
        unpk(acc[j][1], e1, o1);
        unpk(acc[j][2], e2, o2);
        unpk(acc[j][3], e3, o3);
        *reinterpret_cast<float4*>(obase + (size_t)(2 * j + 0) * WW) = make_float4(e0, e1, e2, e3);
        *reinterpret_cast<float4*>(obase + (size_t)(2 * j + 1) * WW) = make_float4(o0, o1, o2, o3);
    }
}

// ---------------------------------------------------------------------------
extern "C" void kernel_launch(void* const* d_in, const int* in_sizes, int n_in,
                              void* d_out, int out_size) {
    const float* K     = (const float*)d_in[0];
    const float* basis = (const float*)d_in[1];
    float* out = (float*)d_out;
    (void)in_sizes; (void)n_in; (void)out_size;

    extract_factors<<<128, 256>>>(basis);

    dim3 g1(2, BC);
    stage1<<<g1, 256>>>(K);

    dim3 g2(HH / SROWS, BC);
    fused_stage<<<g2, 128>>>(out);
}

// round 13
// speedup vs baseline: 1.6069x; 1.6069x over previous
#include <cuda_runtime.h>
#include <cstdint>

// B=8, C=16, H=512, W=512, M=N=15
//   K:     [128, 16, 16]  f32
//   basis: [262144, 16, 16] f32, separable: basis[h*W+w,p,q] = Bu[h,p]*Bv[w,q]
//   out:   [128, 512, 512] f32
//
// Bu[h,p] = sum_q basis[h*W, p, q]; Bv[w,q] = sum_p basis[w, p, q]
// T[bc,p,w] = sum_q K[bc,p,q]*Bv[w,q];  out[bc,h,w] = sum_p Bu[h,p]*T[bc,p,w]

#define HH 512
#define WW 512
#define PP 16
#define QQ 16
#define BC 128
#define ROWS 64

__device__ float g_But[PP * HH];      // Bu transposed: [p][h], 32 KB
__device__ float g_T[BC * PP * WW];   // T: [bc][p][w], 4 MB (L2-resident)

__device__ __forceinline__ unsigned long long pk(float a, float b) {
    unsigned long long r;
    asm("mov.b64 %0, {%1, %2};" : "=l"(r) : "f"(a), "f"(b));
    return r;
}
__device__ __forceinline__ void fma2(unsigned long long& d, unsigned long long a,
                                     unsigned long long b) {
    asm("fma.rn.f32x2 %0, %1, %2, %0;" : "+l"(d) : "l"(a), "l"(b));
}
__device__ __forceinline__ void unpk(unsigned long long v, float& a, float& b) {
    asm("mov.b64 {%0, %1}, %2;" : "=f"(a), "=f"(b) : "l"(v));
}

// ---------------------------------------------------------------------------
// Kernel P (merged prepass), 128 blocks x 256 threads:
//   blocks 0..63  : Bu extraction (warp-per-h-row, shfl) -> g_But
//   blocks 64..127: Bv for 8 w-rows (warp-per-row, shfl) -> smem, then
//                   T[bc, p, w-strip] for ALL bc (K chunked through smem)
// ---------------------------------------------------------------------------
__global__ __launch_bounds__(256) void prepass(const float* __restrict__ K,
                                               const float* __restrict__ basis) {
    int tid = threadIdx.x;
    int warp = tid >> 5, lane = tid & 31;

    if (blockIdx.x < 64) {
        // ---- Bu extraction ----
        int h = blockIdx.x * 8 + warp;
        const float4* r4 = reinterpret_cast<const float4*>(basis + (size_t)h * WW * (PP * QQ));
        float4 a = r4[lane * 2];
        float4 b = r4[lane * 2 + 1];
        float s = (a.x + a.y) + (a.z + a.w) + (b.x + b.y) + (b.z + b.w);
        s += __shfl_xor_sync(0xffffffffu, s, 1);   // lanes (2k,2k+1) cover p=k
        if ((lane & 1) == 0) g_But[(lane >> 1) * HH + h] = s;
        return;
    }

    // ---- Bv + T for w-strip [w0, w0+8) ----
    int w0 = (blockIdx.x - 64) * 8;

    __shared__ float sBv[8][QQ];
    __shared__ float sK[16 * PP * QQ];   // 16 bc rows, 16 KB

    {   // Bv row per warp
        const float4* r4 = reinterpret_cast<const float4*>(basis + (size_t)(w0 + warp) * (PP * QQ));
        float4 a = r4[lane * 2];
        float4 b = r4[lane * 2 + 1];
        // lane l: p = l>>1, q = (l&1)*8 + j; butterfly over p (offsets 2..16)
        #pragma unroll
        for (int off = 2; off <= 16; off <<= 1) {
            a.x += __shfl_xor_sync(0xffffffffu, a.x, off);
            a.y += __shfl_xor_sync(0xffffffffu, a.y, off);
            a.z += __shfl_xor_sync(0xffffffffu, a.z, off);
            a.w += __shfl_xor_sync(0xffffffffu, a.w, off);
            b.x += __shfl_xor_sync(0xffffffffu, b.x, off);
            b.y += __shfl_xor_sync(0xffffffffu, b.y, off);
            b.z += __shfl_xor_sync(0xffffffffu, b.z, off);
            b.w += __shfl_xor_sync(0xffffffffu, b.w, off);
        }
        if (lane < 2) {
            int q0 = lane * 8;
            sBv[warp][q0 + 0] = a.x; sBv[warp][q0 + 1] = a.y;
            sBv[warp][q0 + 2] = a.z; sBv[warp][q0 + 3] = a.w;
            sBv[warp][q0 + 4] = b.x; sBv[warp][q0 + 5] = b.y;
            sBv[warp][q0 + 6] = b.z; sBv[warp][q0 + 7] = b.w;
        }
    }
    __syncthreads();

    // thread t -> (w = t&7, p = (t>>3)&15, bcl = t>>7 in {0,1})
    int w = tid & 7, p = (tid >> 3) & 15, bcl = tid >> 7;
    float bv[QQ];
    #pragma unroll
    for (int q = 0; q < QQ; ++q) bv[q] = sBv[w][q];

    for (int chunk = 0; chunk < BC; chunk += 16) {
        __syncthreads();   // protect sK from readers of previous chunk
        {   // stage K[chunk..chunk+16): 1024 float4, 4 per thread
            const float4* src = reinterpret_cast<const float4*>(K + (size_t)chunk * (PP * QQ));
            float4* dst = reinterpret_cast<float4*>(sK);
            #pragma unroll
            for (int i = 0; i < 4; ++i) dst[tid + 256 * i] = src[tid + 256 * i];
        }
        __syncthreads();

        #pragma unroll
        for (int j = 0; j < 8; ++j) {
            int bcr = bcl * 8 + j;               // 0..15 within chunk
            const float* kk = sK + bcr * (PP * QQ) + p * QQ;
            float s = 0.f;
            #pragma unroll
            for (int q = 0; q < QQ; ++q) s = fmaf(kk[q], bv[q], s);
            g_T[(size_t)(chunk + bcr) * PP * WW + p * WW + w0 + w] = s;
        }
    }
}

// ---------------------------------------------------------------------------
// Kernel C (R5-proven fused): out[bc,h,w] = sum_p Bu[h,p] * T[bc,p,w]
//   grid (H/ROWS=8, BC), 128 threads; thread t owns w = 4t..4t+3.
//   Accumulator pairs packed over h; Bu = natural pair via broadcast LDS.128;
//   T dup'd once into register pairs.
// ---------------------------------------------------------------------------
__global__ __launch_bounds__(128) void fused_stage(float* __restrict__ out) {
    int bc = blockIdx.y;
    int h0 = blockIdx.x * ROWS;
    int t = threadIdx.x;

    __shared__ float sBu[PP * ROWS];   // [p][hh], 4 KB

    // Stage Bu tile (coalesced float4 copy)
    {
        const float4* src = reinterpret_cast<const float4*>(g_But);
        float4* dst = reinterpret_cast<float4*>(sBu);
        #pragma unroll
        for (int i = t; i < PP * ROWS / 4; i += 128) {
            int p = i >> 4, c = i & 15;
            dst[i] = src[(p * HH + h0) / 4 + c];
        }
    }

    // Load T[p][4t..4t+3] and duplicate into register pairs
    unsigned long long Td[PP][4];
    {
        const float4* t4 = reinterpret_cast<const float4*>(g_T + (size_t)bc * PP * WW);
        #pragma unroll
        for (int p = 0; p < PP; ++p) {
            float4 tl = t4[p * (WW / 4) + t];
            Td[p][0] = pk(tl.x, tl.x);
            Td[p][1] = pk(tl.y, tl.y);
            Td[p][2] = pk(tl.z, tl.z);
            Td[p][3] = pk(tl.w, tl.w);
        }
    }
    __syncthreads();

    float* obase = out + (size_t)bc * HH * WW + (size_t)h0 * WW + 4 * t;

    #pragma unroll 2
    for (int g = 0; g < ROWS; g += 4) {
        unsigned long long acc[4][2];
        #pragma unroll
        for (int w = 0; w < 4; ++w) { acc[w][0] = 0ull; acc[w][1] = 0ull; }

        #pragma unroll
        for (int p = 0; p < PP; ++p) {
            // Broadcast LDS.128: Bu for h = h0+g..h0+g+3, as 2 natural pairs
            ulonglong2 v = *reinterpret_cast<const ulonglong2*>(&sBu[p * ROWS + g]);
            fma2(acc[0][0], v.x, Td[p][0]);
            fma2(acc[1][0], v.x, Td[p][1]);
            fma2(acc[2][0], v.x, Td[p][2]);
            fma2(acc[3][0], v.x, Td[p][3]);
            fma2(acc[0][1], v.y, Td[p][0]);
            fma2(acc[1][1], v.y, Td[p][1]);
            fma2(acc[2][1], v.y, Td[p][2]);
            fma2(acc[3][1], v.y, Td[p][3]);
        }

        float r0[4], r1[4], r2[4], r3[4];
        #pragma unroll
        for (int w = 0; w < 4; ++w) {
            unpk(acc[w][0], r0[w], r1[w]);   // rows g, g+1
            unpk(acc[w][1], r2[w], r3[w]);   // rows g+2, g+3
        }
        *reinterpret_cast<float4*>(obase + (size_t)(g + 0) * WW) = make_float4(r0[0], r0[1], r0[2], r0[3]);
        *reinterpret_cast<float4*>(obase + (size_t)(g + 1) * WW) = make_float4(r1[0], r1[1], r1[2], r1[3]);
        *reinterpret_cast<float4*>(obase + (size_t)(g + 2) * WW) = make_float4(r2[0], r2[1], r2[2], r2[3]);
        *reinterpret_cast<float4*>(obase + (size_t)(g + 3) * WW) = make_float4(r3[0], r3[1], r3[2], r3[3]);
    }
}

// ---------------------------------------------------------------------------
extern "C" void kernel_launch(void* const* d_in, const int* in_sizes, int n_in,
                              void* d_out, int out_size) {
    const float* K     = (const float*)d_in[0];
    const float* basis = (const float*)d_in[1];
    float* out = (float*)d_out;
    (void)in_sizes; (void)n_in; (void)out_size;

    prepass<<<128, 256>>>(K, basis);

    dim3 g2(HH / ROWS, BC);
    fused_stage<<<g2, 128>>>(out);
}

// round 14
// speedup vs baseline: 1.8376x; 1.1436x over previous
#include <cuda_runtime.h>
#include <cstdint>

// B=8, C=16, H=512, W=512, M=N=15
//   K:     [128, 16, 16]  f32
//   basis: [262144, 16, 16] f32, separable: basis[h*W+w,p,q] = Bu[h,p]*Bv[w,q]
//   out:   [128, 512, 512] f32
//
// Bu[h,p] = sum_q basis[h*W, p, q]; Bv[w,q] = sum_p basis[w, p, q]
// T[bc,p,w] = sum_q K[bc,p,q]*Bv[w,q];  out[bc,h,w] = sum_p Bu[h,p]*T[bc,p,w]

#define HH 512
#define WW 512
#define PP 16
#define QQ 16
#define BC 128
#define ROWS 64

__device__ float g_But[PP * HH];      // Bu transposed: [p][h], 32 KB
__device__ float g_T[BC * PP * WW];   // T: [bc][p][w], 4 MB (L2-resident)

__device__ __forceinline__ unsigned long long pk(float a, float b) {
    unsigned long long r;
    asm("mov.b64 %0, {%1, %2};" : "=l"(r) : "f"(a), "f"(b));
    return r;
}
__device__ __forceinline__ void fma2(unsigned long long& d, unsigned long long a,
                                     unsigned long long b) {
    asm("fma.rn.f32x2 %0, %1, %2, %0;" : "+l"(d) : "l"(a), "l"(b));
}
__device__ __forceinline__ void unpk(unsigned long long v, float& a, float& b) {
    asm("mov.b64 {%0, %1}, %2;" : "=f"(a), "=f"(b) : "l"(v));
}

// ---------------------------------------------------------------------------
// Kernel P (prepass, 576 blocks x 256 threads, NO serial chunk loop):
//   blocks 0..63   : Bu extraction (warp-per-h-row, shfl) -> g_But
//   blocks 64..575 : idx = blk-64; w-strip = (idx>>3)*8, bc-group = (idx&7)*16.
//                    Compute Bv for 8 w rows (warp-per-row shfl, redundant
//                    across bc-groups — L2-hit cheap), stage 16 KB of K,
//                    ONE sync, each thread computes 8 T values.
// ---------------------------------------------------------------------------
__global__ __launch_bounds__(256) void prepass(const float* __restrict__ K,
                                               const float* __restrict__ basis) {
    int tid = threadIdx.x;
    int warp = tid >> 5, lane = tid & 31;

    if (blockIdx.x < 64) {
        // ---- Bu extraction ----
        int h = blockIdx.x * 8 + warp;
        const float4* r4 = reinterpret_cast<const float4*>(basis + (size_t)h * WW * (PP * QQ));
        float4 a = r4[lane * 2];
        float4 b = r4[lane * 2 + 1];
        float s = (a.x + a.y) + (a.z + a.w) + (b.x + b.y) + (b.z + b.w);
        s += __shfl_xor_sync(0xffffffffu, s, 1);   // lanes (2k,2k+1) cover p=k
        if ((lane & 1) == 0) g_But[(lane >> 1) * HH + h] = s;
        return;
    }

    int idx = blockIdx.x - 64;       // 0..511
    int w0  = (idx >> 3) * 8;        // w-strip
    int bc0 = (idx & 7) * 16;        // bc-group

    __shared__ float sBv[8][QQ + 1];     // padded: conflict-free reads
    __shared__ float sK[16 * PP * QQ];   // 16 bc rows, 16 KB

    {   // Bv row per warp (w = w0 + warp)
        const float4* r4 = reinterpret_cast<const float4*>(basis + (size_t)(w0 + warp) * (PP * QQ));
        float4 a = r4[lane * 2];
        float4 b = r4[lane * 2 + 1];
        // lane l: p = l>>1, q = (l&1)*8 + j; butterfly over p (offsets 2..16)
        #pragma unroll
        for (int off = 2; off <= 16; off <<= 1) {
            a.x += __shfl_xor_sync(0xffffffffu, a.x, off);
            a.y += __shfl_xor_sync(0xffffffffu, a.y, off);
            a.z += __shfl_xor_sync(0xffffffffu, a.z, off);
            a.w += __shfl_xor_sync(0xffffffffu, a.w, off);
            b.x += __shfl_xor_sync(0xffffffffu, b.x, off);
            b.y += __shfl_xor_sync(0xffffffffu, b.y, off);
            b.z += __shfl_xor_sync(0xffffffffu, b.z, off);
            b.w += __shfl_xor_sync(0xffffffffu, b.w, off);
        }
        if (lane < 2) {
            int q0 = lane * 8;
            sBv[warp][q0 + 0] = a.x; sBv[warp][q0 + 1] = a.y;
            sBv[warp][q0 + 2] = a.z; sBv[warp][q0 + 3] = a.w;
            sBv[warp][q0 + 4] = b.x; sBv[warp][q0 + 5] = b.y;
            sBv[warp][q0 + 6] = b.z; sBv[warp][q0 + 7] = b.w;
        }
    }

    {   // stage K[bc0..bc0+16): 1024 float4, 4 per thread, coalesced
        const float4* src = reinterpret_cast<const float4*>(K + (size_t)bc0 * (PP * QQ));
        float4* dst = reinterpret_cast<float4*>(sK);
        #pragma unroll
        for (int i = 0; i < 4; ++i) dst[tid + 256 * i] = src[tid + 256 * i];
    }
    __syncthreads();

    // thread t -> w = t&7, ph = (t>>3)&1 (p-half), bcl = t>>4
    int w = tid & 7;
    int ph = (tid >> 3) & 1;
    int bcl = tid >> 4;

    float bv[QQ];
    #pragma unroll
    for (int q = 0; q < QQ; ++q) bv[q] = sBv[w][q];

    const float* kk = sK + bcl * (PP * QQ);
    float* tb = g_T + (size_t)(bc0 + bcl) * PP * WW + w0 + w;
    #pragma unroll
    for (int j = 0; j < 8; ++j) {
        int p = ph * 8 + j;
        float s = 0.f;
        #pragma unroll
        for (int q = 0; q < QQ; ++q) s = fmaf(kk[p * QQ + q], bv[q], s);
        tb[(size_t)p * WW] = s;
    }
}

// ---------------------------------------------------------------------------
// Kernel C (R13-proven fused, unchanged): out[bc,h,w] = sum_p Bu[h,p]*T[bc,p,w]
//   grid (H/ROWS=8, BC), 128 threads; thread t owns w = 4t..4t+3.
//   Accumulator pairs packed over h; Bu = natural pair via broadcast LDS.128;
//   T dup'd once into register pairs.
// ---------------------------------------------------------------------------
__global__ __launch_bounds__(128) void fused_stage(float* __restrict__ out) {
    int bc = blockIdx.y;
    int h0 = blockIdx.x * ROWS;
    int t = threadIdx.x;

    __shared__ float sBu[PP * ROWS];   // [p][hh], 4 KB

    // Stage Bu tile (coalesced float4 copy)
    {
        const float4* src = reinterpret_cast<const float4*>(g_But);
        float4* dst = reinterpret_cast<float4*>(sBu);
        #pragma unroll
        for (int i = t; i < PP * ROWS / 4; i += 128) {
            int p = i >> 4, c = i & 15;
            dst[i] = src[(p * HH + h0) / 4 + c];
        }
    }

    // Load T[p][4t..4t+3] and duplicate into register pairs
    unsigned long long Td[PP][4];
    {
        const float4* t4 = reinterpret_cast<const float4*>(g_T + (size_t)bc * PP * WW);
        #pragma unroll
        for (int p = 0; p < PP; ++p) {
            float4 tl = t4[p * (WW / 4) + t];
            Td[p][0] = pk(tl.x, tl.x);
            Td[p][1] = pk(tl.y, tl.y);
            Td[p][2] = pk(tl.z, tl.z);
            Td[p][3] = pk(tl.w, tl.w);
        }
    }
    __syncthreads();

    float* obase = out + (size_t)bc * HH * WW + (size_t)h0 * WW + 4 * t;

    #pragma unroll 2
    for (int g = 0; g < ROWS; g += 4) {
        unsigned long long acc[4][2];
        #pragma unroll
        for (int w = 0; w < 4; ++w) { acc[w][0] = 0ull; acc[w][1] = 0ull; }

        #pragma unroll
        for (int p = 0; p < PP; ++p) {
            // Broadcast LDS.128: Bu for h = h0+g..h0+g+3, as 2 natural pairs
            ulonglong2 v = *reinterpret_cast<const ulonglong2*>(&sBu[p * ROWS + g]);
            fma2(acc[0][0], v.x, Td[p][0]);
            fma2(acc[1][0], v.x, Td[p][1]);
            fma2(acc[2][0], v.x, Td[p][2]);
            fma2(acc[3][0], v.x, Td[p][3]);
            fma2(acc[0][1], v.y, Td[p][0]);
            fma2(acc[1][1], v.y, Td[p][1]);
            fma2(acc[2][1], v.y, Td[p][2]);
            fma2(acc[3][1], v.y, Td[p][3]);
        }

        float r0[4], r1[4], r2[4], r3[4];
        #pragma unroll
        for (int w = 0; w < 4; ++w) {
            unpk(acc[w][0], r0[w], r1[w]);   // rows g, g+1
            unpk(acc[w][1], r2[w], r3[w]);   // rows g+2, g+3
        }
        *reinterpret_cast<float4*>(obase + (size_t)(g + 0) * WW) = make_float4(r0[0], r0[1], r0[2], r0[3]);
        *reinterpret_cast<float4*>(obase + (size_t)(g + 1) * WW) = make_float4(r1[0], r1[1], r1[2], r1[3]);
        *reinterpret_cast<float4*>(obase + (size_t)(g + 2) * WW) = make_float4(r2[0], r2[1], r2[2], r2[3]);
        *reinterpret_cast<float4*>(obase + (size_t)(g + 3) * WW) = make_float4(r3[0], r3[1], r3[2], r3[3]);
    }
}

// ---------------------------------------------------------------------------
extern "C" void kernel_launch(void* const* d_in, const int* in_sizes, int n_in,
                              void* d_out, int out_size) {
    const float* K     = (const float*)d_in[0];
    const float* basis = (const float*)d_in[1];
    float* out = (float*)d_out;
    (void)in_sizes; (void)n_in; (void)out_size;

    prepass<<<576, 256>>>(K, basis);

    dim3 g2(HH / ROWS, BC);
    fused_stage<<<g2, 128>>>(out);
}